// round 1
// baseline (speedup 1.0000x reference)
#include <cuda_runtime.h>
#include <cuda_bf16.h>
#include <math.h>

// Problem constants
#define B_   8
#define T_   4096
#define H_   1024
#define NH_  16
#define HD_  64
#define MTOT (B_ * T_)          // 32768
#define SCALE 0.125f            // 1/sqrt(64)

// ---------------- scratch (device globals; no allocation allowed) ----------------
__device__ float g_q[(size_t)MTOT * H_];       // 128 MB
__device__ float g_k[(size_t)MTOT * H_];       // 128 MB
__device__ float g_score[(size_t)B_ * NH_ * T_]; // 2 MB
__device__ float g_pq[B_ * H_];
__device__ float g_pk[B_ * H_];

// ---------------- big GEMM: C = (A [* ascale_row]) @ W^T + bias [+ addend] -------
// A: [M,K] row-major, W: [N,K] row-major. MODE 0: plain + bias. MODE 1: A scaled
// per-batch by ascale[b,K] (b = row/T_), plus bias, plus addend (residual).
#define BM 128
#define BN 128
#define BK 16
#define TM 8
#define TN 8

template <int MODE>
__global__ __launch_bounds__(256)
void gemm_nt(const float* __restrict__ A, const float* __restrict__ W,
             const float* __restrict__ bias, const float* __restrict__ ascale,
             const float* __restrict__ addend, float* __restrict__ C,
             int M, int N, int K)
{
    __shared__ float As[BK][BM];
    __shared__ float Bs[BK][BN];

    const int tid = threadIdx.x;
    const int bm  = blockIdx.y * BM;
    const int bn  = blockIdx.x * BN;
    const int tx  = tid & 15;       // 0..15 -> col group
    const int ty  = tid >> 4;       // 0..15 -> row group

    const float* sc = nullptr;
    if (MODE == 1) sc = ascale + (size_t)(bm / T_) * K;   // BM divides T_, single batch per block

    float acc[TM][TN];
    #pragma unroll
    for (int i = 0; i < TM; i++)
        #pragma unroll
        for (int j = 0; j < TN; j++) acc[i][j] = 0.f;

    for (int k0 = 0; k0 < K; k0 += BK) {
        // load A tile (128x16) and W tile (128x16), transposed into smem
        #pragma unroll
        for (int l = 0; l < 2; l++) {
            int idx = tid * 2 + l;          // 0..511
            int row = idx >> 2;             // 0..127
            int c4  = (idx & 3) * 4;        // 0,4,8,12
            float4 va = *(const float4*)(A + (size_t)(bm + row) * K + k0 + c4);
            if (MODE == 1) {
                va.x *= sc[k0 + c4 + 0];
                va.y *= sc[k0 + c4 + 1];
                va.z *= sc[k0 + c4 + 2];
                va.w *= sc[k0 + c4 + 3];
            }
            As[c4 + 0][row] = va.x; As[c4 + 1][row] = va.y;
            As[c4 + 2][row] = va.z; As[c4 + 3][row] = va.w;

            float4 vb = *(const float4*)(W + (size_t)(bn + row) * K + k0 + c4);
            Bs[c4 + 0][row] = vb.x; Bs[c4 + 1][row] = vb.y;
            Bs[c4 + 2][row] = vb.z; Bs[c4 + 3][row] = vb.w;
        }
        __syncthreads();

        #pragma unroll
        for (int kk = 0; kk < BK; kk++) {
            float a[TM], b[TN];
            #pragma unroll
            for (int i = 0; i < TM; i++) a[i] = As[kk][ty * TM + i];
            #pragma unroll
            for (int j = 0; j < TN; j++) b[j] = Bs[kk][tx * TN + j];
            #pragma unroll
            for (int i = 0; i < TM; i++)
                #pragma unroll
                for (int j = 0; j < TN; j++) acc[i][j] = fmaf(a[i], b[j], acc[i][j]);
        }
        __syncthreads();
    }

    // epilogue
    const int m0 = bm + ty * TM;
    const int n0 = bn + tx * TN;
    #pragma unroll
    for (int i = 0; i < TM; i++) {
        const size_t rowoff = (size_t)(m0 + i) * N;
        #pragma unroll
        for (int j4 = 0; j4 < TN / 4; j4++) {
            int col = n0 + j4 * 4;
            float4 v;
            v.x = acc[i][j4 * 4 + 0] + bias[col + 0];
            v.y = acc[i][j4 * 4 + 1] + bias[col + 1];
            v.z = acc[i][j4 * 4 + 2] + bias[col + 2];
            v.w = acc[i][j4 * 4 + 3] + bias[col + 3];
            if (MODE == 1) {
                float4 ad = *(const float4*)(addend + rowoff + col);
                v.x += ad.x; v.y += ad.y; v.z += ad.z; v.w += ad.w;
            }
            *(float4*)(C + rowoff + col) = v;
        }
    }
}

// ---------------- score kernel: score[b,h,t] = SCALE*(dot(X[b,t,:]*s[b,:], Wl[h,:]) + bl[h]) + madd
__global__ __launch_bounds__(256)
void score_kernel(const float* __restrict__ X,      // [B,T,H]
                  const float* __restrict__ Wl,     // [NH,H]
                  const float* __restrict__ bl,     // [NH]
                  const float* __restrict__ s,      // [B,H] or null
                  const float* __restrict__ mask,   // [B,T]
                  float* __restrict__ score)        // [B,NH,T]
{
    __shared__ float xs[H_];
    const int bt = blockIdx.x;            // 0..MTOT-1
    const int b  = bt / T_;
    const int t  = bt % T_;
    const int tid = threadIdx.x;

    const float* xrow = X + (size_t)bt * H_;
    if (s) {
        const float* sb = s + (size_t)b * H_;
        for (int j = tid; j < H_; j += 256) xs[j] = xrow[j] * sb[j];
    } else {
        for (int j = tid; j < H_; j += 256) xs[j] = xrow[j];
    }
    __syncthreads();

    const float madd = (1.f - mask[bt]) * -10000.f;
    const int warp = tid >> 5, lane = tid & 31;
    #pragma unroll
    for (int h = warp; h < NH_; h += 8) {
        const float* w = Wl + (size_t)h * H_;
        float sum = 0.f;
        for (int j = lane; j < H_; j += 32) sum = fmaf(xs[j], w[j], sum);
        #pragma unroll
        for (int o = 16; o; o >>= 1) sum += __shfl_xor_sync(0xffffffffu, sum, o);
        if (lane == 0)
            score[((size_t)b * NH_ + h) * T_ + t] = SCALE * (sum + bl[h]) + madd;
    }
}

// ---------------- softmax over T + pooled[b,hd] = (Σ_t w_t X[b,t,hd]) [* mul[b,hd]]
__global__ __launch_bounds__(256)
void softpool_kernel(const float* __restrict__ score, // [B,NH,T]
                     const float* __restrict__ X,     // [B,T,H]
                     const float* __restrict__ mul,   // [B,H] or null
                     float* __restrict__ pooled)      // [B,H]
{
    __shared__ float w[T_];        // 16 KB
    __shared__ float red[256];
    const int bh = blockIdx.x;
    const int b = bh / NH_, h = bh % NH_;
    const int tid = threadIdx.x;

    const float* sc = score + (size_t)bh * T_;
    float mx = -INFINITY;
    for (int t = tid; t < T_; t += 256) { float v = sc[t]; w[t] = v; mx = fmaxf(mx, v); }
    red[tid] = mx; __syncthreads();
    #pragma unroll
    for (int s2 = 128; s2; s2 >>= 1) {
        if (tid < s2) red[tid] = fmaxf(red[tid], red[tid + s2]);
        __syncthreads();
    }
    mx = red[0]; __syncthreads();

    float sum = 0.f;
    for (int t = tid; t < T_; t += 256) { float e = __expf(w[t] - mx); w[t] = e; sum += e; }
    red[tid] = sum; __syncthreads();
    #pragma unroll
    for (int s2 = 128; s2; s2 >>= 1) {
        if (tid < s2) red[tid] += red[tid + s2];
        __syncthreads();
    }
    const float inv = 1.f / red[0];
    __syncthreads();

    // pool: d = tid%64, 4 groups over t
    const int d = tid & 63, g = tid >> 6;
    float acc = 0.f;
    const float* xp = X + (size_t)b * T_ * H_ + (size_t)h * HD_ + d;
    for (int t = g; t < T_; t += 4) acc = fmaf(w[t], xp[(size_t)t * H_], acc);
    red[g * 64 + d] = acc; __syncthreads();
    if (g == 0) {
        float v = (red[d] + red[64 + d] + red[128 + d] + red[192 + d]) * inv;
        if (mul) v *= mul[(size_t)b * H_ + h * HD_ + d];
        pooled[(size_t)b * H_ + h * HD_ + d] = v;
    }
}

// ---------------- launch ----------------
extern "C" void kernel_launch(void* const* d_in, const int* in_sizes, int n_in,
                              void* d_out, int out_size)
{
    const float* hs   = (const float*)d_in[0];
    const float* mask = (const float*)d_in[1];
    const float* Wq   = (const float*)d_in[2];
    const float* bq   = (const float*)d_in[3];
    const float* Wk   = (const float*)d_in[4];
    const float* bk   = (const float*)d_in[5];
    const float* Wql  = (const float*)d_in[6];
    const float* bql  = (const float*)d_in[7];
    const float* Wkl  = (const float*)d_in[8];
    const float* bkl  = (const float*)d_in[9];
    const float* Wt   = (const float*)d_in[10];
    const float* bt   = (const float*)d_in[11];
    float* out = (float*)d_out;

    float *q, *k, *score, *pq, *pk;
    cudaGetSymbolAddress((void**)&q, g_q);
    cudaGetSymbolAddress((void**)&k, g_k);
    cudaGetSymbolAddress((void**)&score, g_score);
    cudaGetSymbolAddress((void**)&pq, g_pq);
    cudaGetSymbolAddress((void**)&pk, g_pk);

    dim3 gg(H_ / BN, MTOT / BM);

    // 1. q = hs @ Wq^T + bq ; 2. k = hs @ Wk^T + bk
    gemm_nt<0><<<gg, 256>>>(hs, Wq, bq, nullptr, nullptr, q, MTOT, H_, H_);
    gemm_nt<0><<<gg, 256>>>(hs, Wk, bk, nullptr, nullptr, k, MTOT, H_, H_);

    // 3. q scores -> softmax -> pooled_q (flat)
    score_kernel<<<MTOT, 256>>>(q, Wql, bql, nullptr, mask, score);
    softpool_kernel<<<B_ * NH_, 256>>>(score, q, nullptr, pq);

    // 4. k scores with pq-modulated rows -> softmax -> pooled_k = pq * pool(k)
    score_kernel<<<MTOT, 256>>>(k, Wkl, bkl, pq, mask, score);
    softpool_kernel<<<B_ * NH_, 256>>>(score, k, pq, pk);

    // 5. out = (q * pk_row) @ Wt^T + bt + q
    gemm_nt<1><<<gg, 256>>>(q, Wt, bt, pk, q, out, MTOT, H_, H_);
}

// round 3
// speedup vs baseline: 2.1410x; 2.1410x over previous
#include <cuda_runtime.h>
#include <cuda_bf16.h>
#include <cstdint>
#include <math.h>

// Problem constants
#define B_   8
#define T_   4096
#define H_   1024
#define NH_  16
#define HD_  64
#define MTOT (B_ * T_)          // 32768
#define SCALE 0.125f            // 1/sqrt(64)
#define NCH  8                  // pool chunks
#define TCH  (T_ / NCH)         // 512

// ---------------- scratch ----------------
__device__ float  g_q[(size_t)MTOT * H_];         // 128 MB
__device__ float  g_k[(size_t)MTOT * H_];         // 128 MB
__device__ float  g_score[(size_t)B_ * NH_ * T_]; // 2 MB
__device__ float  g_pq[B_ * H_];
__device__ float  g_pk[B_ * H_];
__device__ float2 g_stat[B_ * NH_];
__device__ float  g_part[B_ * NH_ * NCH * HD_];

// =================================================================
// TF32 tensor-core GEMM:  C = (A [*ascale]) @ W^T + bias [+ addend]
// A [M,K] row-major, W [N,K] row-major.
// MODE 0: dual-output (W0->C0, W1->C1), plain.
// MODE 1: A scaled per-batch by ascale[b,K], plus addend (residual).
// =================================================================
#define BM 128
#define BN 128
#define BKK 32

__device__ __forceinline__ uint32_t f2tf32(float f) {
    uint32_t r;
    asm("cvt.rna.tf32.f32 %0, %1;" : "=r"(r) : "f"(f));
    return r;
}

__device__ __forceinline__ void mma_tf32(float* c, const uint32_t* a, const uint32_t* b) {
    asm volatile(
        "mma.sync.aligned.m16n8k8.row.col.f32.tf32.tf32.f32 "
        "{%0,%1,%2,%3}, {%4,%5,%6,%7}, {%8,%9}, {%0,%1,%2,%3};"
        : "+f"(c[0]), "+f"(c[1]), "+f"(c[2]), "+f"(c[3])
        : "r"(a[0]), "r"(a[1]), "r"(a[2]), "r"(a[3]),
          "r"(b[0]), "r"(b[1]));
}

template <int MODE>
__global__ __launch_bounds__(256, 1)
void gemm_tc(const float* __restrict__ A,
             const float* __restrict__ W0, const float* __restrict__ bias0,
             const float* __restrict__ W1, const float* __restrict__ bias1,
             const float* __restrict__ ascale, const float* __restrict__ addend,
             float* __restrict__ C0, float* __restrict__ C1)
{
    const int K = H_, N = H_;
    __shared__ uint32_t As[BM][BKK + 4];
    __shared__ uint32_t Bs[BN][BKK + 4];

    const int tid = threadIdx.x;
    const int bm  = blockIdx.y * BM;

    const float* W = W0; const float* bias = bias0; float* C = C0;
    int bn;
    if (MODE == 0) {
        int bx = blockIdx.x;
        const int half = N / BN;
        if (bx >= half) { W = W1; bias = bias1; C = C1; bn = (bx - half) * BN; }
        else bn = bx * BN;
    } else {
        bn = blockIdx.x * BN;
    }

    const float* sc = (MODE == 1) ? (ascale + (size_t)(bm / T_) * K) : nullptr;

    // global-load mapping: row = tid/2 (0..127), colGroup = tid%2; 4 float4 each
    const int grow = tid >> 1;
    const int gcg  = (tid & 1) * 16;   // float offset base of the 4 float4s

    const int wid = tid >> 5, lane = tid & 31;
    const int warp_m = wid >> 2, warp_n = wid & 3;  // 2 x 4 warps
    const int gid = lane >> 2, lm = lane & 3;

    float acc[4][4][4];
    #pragma unroll
    for (int i = 0; i < 4; i++)
        #pragma unroll
        for (int j = 0; j < 4; j++)
            #pragma unroll
            for (int r = 0; r < 4; r++) acc[i][j][r] = 0.f;

    float4 ra[4], rb[4];

    auto load_tile = [&](int k0) {
        const float* ap = A + (size_t)(bm + grow) * K + k0 + gcg;
        const float* wp = W + (size_t)(bn + grow) * K + k0 + gcg;
        #pragma unroll
        for (int l = 0; l < 4; l++) {
            ra[l] = *(const float4*)(ap + l * 4);
            rb[l] = *(const float4*)(wp + l * 4);
        }
        if (MODE == 1) {
            const float* sp = sc + k0 + gcg;
            #pragma unroll
            for (int l = 0; l < 4; l++) {
                float4 s = *(const float4*)(sp + l * 4);
                ra[l].x *= s.x; ra[l].y *= s.y; ra[l].z *= s.z; ra[l].w *= s.w;
            }
        }
    };
    auto store_tile = [&]() {
        #pragma unroll
        for (int l = 0; l < 4; l++) {
            uint4 a4 = { f2tf32(ra[l].x), f2tf32(ra[l].y), f2tf32(ra[l].z), f2tf32(ra[l].w) };
            uint4 b4 = { f2tf32(rb[l].x), f2tf32(rb[l].y), f2tf32(rb[l].z), f2tf32(rb[l].w) };
            *(uint4*)&As[grow][gcg + l * 4] = a4;
            *(uint4*)&Bs[grow][gcg + l * 4] = b4;
        }
    };

    load_tile(0);
    store_tile();
    __syncthreads();

    const int KT = K / BKK;
    for (int kt = 0; kt < KT; kt++) {
        if (kt + 1 < KT) load_tile((kt + 1) * BKK);

        #pragma unroll
        for (int kk = 0; kk < 4; kk++) {
            const int kb = kk * 8;
            uint32_t af[4][4], bf[4][2];
            #pragma unroll
            for (int mt = 0; mt < 4; mt++) {
                int r = warp_m * 64 + mt * 16 + gid;
                af[mt][0] = As[r][kb + lm];
                af[mt][1] = As[r + 8][kb + lm];
                af[mt][2] = As[r][kb + 4 + lm];
                af[mt][3] = As[r + 8][kb + 4 + lm];
            }
            #pragma unroll
            for (int nt = 0; nt < 4; nt++) {
                int nr = warp_n * 32 + nt * 8 + gid;
                bf[nt][0] = Bs[nr][kb + lm];
                bf[nt][1] = Bs[nr][kb + 4 + lm];
            }
            #pragma unroll
            for (int mt = 0; mt < 4; mt++)
                #pragma unroll
                for (int nt = 0; nt < 4; nt++)
                    mma_tf32(acc[mt][nt], af[mt], bf[nt]);
        }
        __syncthreads();
        if (kt + 1 < KT) {
            store_tile();
            __syncthreads();
        }
    }

    // epilogue
    #pragma unroll
    for (int mt = 0; mt < 4; mt++) {
        #pragma unroll
        for (int nt = 0; nt < 4; nt++) {
            int row0 = bm + warp_m * 64 + mt * 16 + gid;
            int col  = bn + warp_n * 32 + nt * 8 + lm * 2;
            float b0 = bias[col], b1 = bias[col + 1];
            #pragma unroll
            for (int half = 0; half < 2; half++) {
                int row = row0 + half * 8;
                size_t off = (size_t)row * N + col;
                float2 v;
                v.x = acc[mt][nt][half * 2 + 0] + b0;
                v.y = acc[mt][nt][half * 2 + 1] + b1;
                if (MODE == 1) {
                    float2 ad = *(const float2*)(addend + off);
                    v.x += ad.x; v.y += ad.y;
                }
                *(float2*)(C + off) = v;
            }
        }
    }
}

// ---------------- score: score[b,h,t] = SCALE*(dot(X[b,t,:]*s[b,:], Wl[h,:]) + bl[h]) + madd
__global__ __launch_bounds__(256)
void score_kernel(const float* __restrict__ X, const float* __restrict__ Wl,
                  const float* __restrict__ bl, const float* __restrict__ s,
                  const float* __restrict__ mask, float* __restrict__ score)
{
    __shared__ float xs[H_];
    const int bt = blockIdx.x;
    const int b  = bt / T_;
    const int t  = bt % T_;
    const int tid = threadIdx.x;

    const float* xrow = X + (size_t)bt * H_;
    if (s) {
        const float* sb = s + (size_t)b * H_;
        for (int j = tid; j < H_; j += 256) xs[j] = xrow[j] * sb[j];
    } else {
        for (int j = tid; j < H_; j += 256) xs[j] = xrow[j];
    }
    __syncthreads();

    const float madd = (1.f - mask[bt]) * -10000.f;
    const int warp = tid >> 5, lane = tid & 31;
    #pragma unroll
    for (int h = warp; h < NH_; h += 8) {
        const float* w = Wl + (size_t)h * H_;
        float sum = 0.f;
        for (int j = lane; j < H_; j += 32) sum = fmaf(xs[j], w[j], sum);
        #pragma unroll
        for (int o = 16; o; o >>= 1) sum += __shfl_xor_sync(0xffffffffu, sum, o);
        if (lane == 0)
            score[((size_t)b * NH_ + h) * T_ + t] = SCALE * (sum + bl[h]) + madd;
    }
}

// ---------------- softmax stats per (b,h): max + 1/sum(exp)
__global__ __launch_bounds__(256)
void stats_kernel(const float* __restrict__ score, float2* __restrict__ stat)
{
    __shared__ float red[256];
    const int bh = blockIdx.x;
    const int tid = threadIdx.x;
    const float* sc = score + (size_t)bh * T_;

    float mx = -INFINITY;
    for (int t = tid; t < T_; t += 256) mx = fmaxf(mx, sc[t]);
    red[tid] = mx; __syncthreads();
    #pragma unroll
    for (int s2 = 128; s2; s2 >>= 1) {
        if (tid < s2) red[tid] = fmaxf(red[tid], red[tid + s2]);
        __syncthreads();
    }
    mx = red[0]; __syncthreads();

    float sum = 0.f;
    for (int t = tid; t < T_; t += 256) sum += __expf(sc[t] - mx);
    red[tid] = sum; __syncthreads();
    #pragma unroll
    for (int s2 = 128; s2; s2 >>= 1) {
        if (tid < s2) red[tid] += red[tid + s2];
        __syncthreads();
    }
    if (tid == 0) stat[bh] = make_float2(mx, 1.f / red[0]);
}

// ---------------- chunked pooling: part[bh][chunk][d] = sum_t exp(sc-mx) * X[b,t, h*64+d]
__global__ __launch_bounds__(256)
void pool_kernel(const float* __restrict__ score, const float2* __restrict__ stat,
                 const float* __restrict__ X, float* __restrict__ part)
{
    __shared__ float red[256];
    const int chunk = blockIdx.x;
    const int bh = blockIdx.y;
    const int b = bh / NH_, h = bh % NH_;
    const int tid = threadIdx.x;
    const int d = tid & 63, tg = tid >> 6;

    const float mx = stat[bh].x;
    const float* sc = score + (size_t)bh * T_ + (size_t)chunk * TCH;
    const float* xp = X + (size_t)b * T_ * H_ + (size_t)chunk * TCH * H_ + h * HD_ + d;

    float acc = 0.f;
    for (int t = tg; t < TCH; t += 4)
        acc = fmaf(__expf(sc[t] - mx), xp[(size_t)t * H_], acc);
    red[tid] = acc; __syncthreads();
    if (tg == 0) {
        float v = red[d] + red[64 + d] + red[128 + d] + red[192 + d];
        part[((size_t)bh * NCH + chunk) * HD_ + d] = v;
    }
}

// ---------------- final pooled reduce: pooled[b, h*64+d] = inv * sum_chunks part [* mul]
__global__ __launch_bounds__(64)
void reduce_pool(const float* __restrict__ part, const float2* __restrict__ stat,
                 const float* __restrict__ mul, float* __restrict__ pooled)
{
    const int bh = blockIdx.x;
    const int b = bh / NH_, h = bh % NH_;
    const int d = threadIdx.x;
    const float inv = stat[bh].y;
    float v = 0.f;
    #pragma unroll
    for (int c = 0; c < NCH; c++)
        v += part[((size_t)bh * NCH + c) * HD_ + d];
    v *= inv;
    const size_t o = (size_t)b * H_ + h * HD_ + d;
    if (mul) v *= mul[o];
    pooled[o] = v;
}

// ---------------- launch ----------------
extern "C" void kernel_launch(void* const* d_in, const int* in_sizes, int n_in,
                              void* d_out, int out_size)
{
    const float* hs   = (const float*)d_in[0];
    const float* mask = (const float*)d_in[1];
    const float* Wq   = (const float*)d_in[2];
    const float* bq   = (const float*)d_in[3];
    const float* Wk   = (const float*)d_in[4];
    const float* bk   = (const float*)d_in[5];
    const float* Wql  = (const float*)d_in[6];
    const float* bql  = (const float*)d_in[7];
    const float* Wkl  = (const float*)d_in[8];
    const float* bkl  = (const float*)d_in[9];
    const float* Wt   = (const float*)d_in[10];
    const float* bt   = (const float*)d_in[11];
    float* out = (float*)d_out;

    float *q, *k, *score, *pq, *pk, *part;
    float2* stat;
    cudaGetSymbolAddress((void**)&q, g_q);
    cudaGetSymbolAddress((void**)&k, g_k);
    cudaGetSymbolAddress((void**)&score, g_score);
    cudaGetSymbolAddress((void**)&pq, g_pq);
    cudaGetSymbolAddress((void**)&pk, g_pk);
    cudaGetSymbolAddress((void**)&stat, g_stat);
    cudaGetSymbolAddress((void**)&part, g_part);

    // 1+2. q = hs@Wq^T + bq ; k = hs@Wk^T + bk  (fused dual-output GEMM)
    gemm_tc<0><<<dim3(2 * H_ / BN, MTOT / BM), 256>>>(
        hs, Wq, bq, Wk, bk, nullptr, nullptr, q, k);

    // 3. pooled_q
    score_kernel<<<MTOT, 256>>>(q, Wql, bql, nullptr, mask, score);
    stats_kernel<<<B_ * NH_, 256>>>(score, stat);
    pool_kernel<<<dim3(NCH, B_ * NH_), 256>>>(score, stat, q, part);
    reduce_pool<<<B_ * NH_, 64>>>(part, stat, nullptr, pq);

    // 4. pooled_k (k rows modulated by pq; final multiply by pq)
    score_kernel<<<MTOT, 256>>>(k, Wkl, bkl, pq, mask, score);
    stats_kernel<<<B_ * NH_, 256>>>(score, stat);
    pool_kernel<<<dim3(NCH, B_ * NH_), 256>>>(score, stat, k, part);
    reduce_pool<<<B_ * NH_, 64>>>(part, stat, pq, pk);

    // 5. out = (q * pk_row) @ Wt^T + bt + q
    gemm_tc<1><<<dim3(H_ / BN, MTOT / BM), 256>>>(
        q, Wt, bt, nullptr, nullptr, pk, q, out, nullptr);
}

// round 4
// speedup vs baseline: 2.5386x; 1.1857x over previous
#include <cuda_runtime.h>
#include <cuda_bf16.h>
#include <cuda_fp16.h>
#include <cstdint>
#include <math.h>

// Problem constants
#define B_   8
#define T_   4096
#define H_   1024
#define NH_  16
#define HD_  64
#define MTOT (B_ * T_)          // 32768
#define SCALE 0.125f            // 1/sqrt(64)
#define NCH  8                  // pool chunks
#define TCH  (T_ / NCH)         // 512

// ---------------- scratch ----------------
__device__ float  g_q[(size_t)MTOT * H_];         // 128 MB
__device__ float  g_k[(size_t)MTOT * H_];         // 128 MB
__device__ float  g_score[(size_t)B_ * NH_ * T_]; // 2 MB
__device__ float  g_pq[B_ * H_];
__device__ float  g_pk[B_ * H_];
__device__ float2 g_stat[B_ * NH_];
__device__ float  g_part[B_ * NH_ * NCH * HD_];

// =================================================================
// FP16 tensor-core GEMM (mma.sync m16n8k16 + ldmatrix):
//   C = (A [*ascale]) @ W^T + bias [+ addend]
// A [M,K] row-major fp32, W [N,K] row-major fp32 (converted to fp16 on the fly)
// MODE 0: dual-output (W0->C0, W1->C1). MODE 1: A scaled per-batch + addend.
// =================================================================
#define BM 128
#define BN 128
#define BKK 32
#define APAD 8                   // halves of padding -> 80B row stride (conflict-free for ldmatrix)
#define ROWH (BKK + APAD)        // 40 halves per row

__device__ __forceinline__ void ldsm_x4(uint32_t* r, const void* p) {
    uint32_t addr = (uint32_t)__cvta_generic_to_shared(p);
    asm volatile("ldmatrix.sync.aligned.m8n8.x4.shared.b16 {%0,%1,%2,%3}, [%4];"
                 : "=r"(r[0]), "=r"(r[1]), "=r"(r[2]), "=r"(r[3]) : "r"(addr));
}

__device__ __forceinline__ void mma_f16(float* c, const uint32_t* a, const uint32_t* b) {
    asm volatile(
        "mma.sync.aligned.m16n8k16.row.col.f32.f16.f16.f32 "
        "{%0,%1,%2,%3}, {%4,%5,%6,%7}, {%8,%9}, {%0,%1,%2,%3};"
        : "+f"(c[0]), "+f"(c[1]), "+f"(c[2]), "+f"(c[3])
        : "r"(a[0]), "r"(a[1]), "r"(a[2]), "r"(a[3]),
          "r"(b[0]), "r"(b[1]));
}

template <int MODE>
__global__ __launch_bounds__(256, 1)
void gemm_tc(const float* __restrict__ A,
             const float* __restrict__ W0, const float* __restrict__ bias0,
             const float* __restrict__ W1, const float* __restrict__ bias1,
             const float* __restrict__ ascale, const float* __restrict__ addend,
             float* __restrict__ C0, float* __restrict__ C1)
{
    const int K = H_, N = H_;
    __shared__ __half As[BM][ROWH];
    __shared__ __half Bs[BN][ROWH];

    const int tid = threadIdx.x;
    const int bm  = blockIdx.y * BM;

    const float* W = W0; const float* bias = bias0; float* C = C0;
    int bn;
    if (MODE == 0) {
        int bx = blockIdx.x;
        const int half_ = N / BN;
        if (bx >= half_) { W = W1; bias = bias1; C = C1; bn = (bx - half_) * BN; }
        else bn = bx * BN;
    } else {
        bn = blockIdx.x * BN;
    }

    const float* sc = (MODE == 1) ? (ascale + (size_t)(bm / T_) * K) : nullptr;

    // global-load mapping: row = tid/2 (0..127), col base = (tid%2)*16; 4 float4 each
    const int grow = tid >> 1;
    const int gcg  = (tid & 1) * 16;

    const int wid = tid >> 5, lane = tid & 31;
    const int warp_m = wid >> 2, warp_n = wid & 3;  // 2 x 4 warps, warp tile 64x32
    const int gid = lane >> 2, lm = lane & 3;

    // ldmatrix per-lane source rows/cols
    const int a_r = (lane & 7) + ((lane >> 3) & 1) * 8;   // + mt*16 + warp_m*64
    const int a_c = (lane >> 4) * 8;                      // + kb
    const int b_r = (lane & 7) + ((lane >> 4) & 1) * 8;   // + ntp*16 + warp_n*32
    const int b_c = ((lane >> 3) & 1) * 8;                // + kb

    float acc[4][4][4];
    #pragma unroll
    for (int i = 0; i < 4; i++)
        #pragma unroll
        for (int j = 0; j < 4; j++)
            #pragma unroll
            for (int r = 0; r < 4; r++) acc[i][j][r] = 0.f;

    float4 ra[4], rb[4];

    auto load_tile = [&](int k0) {
        const float* ap = A + (size_t)(bm + grow) * K + k0 + gcg;
        const float* wp = W + (size_t)(bn + grow) * K + k0 + gcg;
        #pragma unroll
        for (int l = 0; l < 4; l++) {
            ra[l] = *(const float4*)(ap + l * 4);
            rb[l] = *(const float4*)(wp + l * 4);
        }
        if (MODE == 1) {
            const float* sp = sc + k0 + gcg;
            #pragma unroll
            for (int l = 0; l < 4; l++) {
                float4 s = *(const float4*)(sp + l * 4);
                ra[l].x *= s.x; ra[l].y *= s.y; ra[l].z *= s.z; ra[l].w *= s.w;
            }
        }
    };
    auto store_tile = [&]() {
        #pragma unroll
        for (int l = 0; l < 4; l++) {
            __half2 alo = __floats2half2_rn(ra[l].x, ra[l].y);
            __half2 ahi = __floats2half2_rn(ra[l].z, ra[l].w);
            __half2 blo = __floats2half2_rn(rb[l].x, rb[l].y);
            __half2 bhi = __floats2half2_rn(rb[l].z, rb[l].w);
            uint2 av, bv;
            av.x = reinterpret_cast<uint32_t&>(alo);
            av.y = reinterpret_cast<uint32_t&>(ahi);
            bv.x = reinterpret_cast<uint32_t&>(blo);
            bv.y = reinterpret_cast<uint32_t&>(bhi);
            *(uint2*)&As[grow][gcg + l * 4] = av;
            *(uint2*)&Bs[grow][gcg + l * 4] = bv;
        }
    };

    load_tile(0);
    store_tile();
    __syncthreads();

    const int KT = K / BKK;
    for (int kt = 0; kt < KT; kt++) {
        if (kt + 1 < KT) load_tile((kt + 1) * BKK);

        #pragma unroll
        for (int kk = 0; kk < 2; kk++) {
            const int kb = kk * 16;
            uint32_t af[4][4], bf[4][2];
            #pragma unroll
            for (int mt = 0; mt < 4; mt++)
                ldsm_x4(af[mt], &As[warp_m * 64 + mt * 16 + a_r][kb + a_c]);
            #pragma unroll
            for (int ntp = 0; ntp < 2; ntp++) {
                uint32_t r4[4];
                ldsm_x4(r4, &Bs[warp_n * 32 + ntp * 16 + b_r][kb + b_c]);
                bf[ntp * 2 + 0][0] = r4[0]; bf[ntp * 2 + 0][1] = r4[1];
                bf[ntp * 2 + 1][0] = r4[2]; bf[ntp * 2 + 1][1] = r4[3];
            }
            #pragma unroll
            for (int mt = 0; mt < 4; mt++)
                #pragma unroll
                for (int nt = 0; nt < 4; nt++)
                    mma_f16(acc[mt][nt], af[mt], bf[nt]);
        }
        __syncthreads();
        if (kt + 1 < KT) {
            store_tile();
            __syncthreads();
        }
    }

    // epilogue
    #pragma unroll
    for (int mt = 0; mt < 4; mt++) {
        #pragma unroll
        for (int nt = 0; nt < 4; nt++) {
            int row0 = bm + warp_m * 64 + mt * 16 + gid;
            int col  = bn + warp_n * 32 + nt * 8 + lm * 2;
            float b0 = bias[col], b1 = bias[col + 1];
            #pragma unroll
            for (int half_ = 0; half_ < 2; half_++) {
                int row = row0 + half_ * 8;
                size_t off = (size_t)row * N + col;
                float2 v;
                v.x = acc[mt][nt][half_ * 2 + 0] + b0;
                v.y = acc[mt][nt][half_ * 2 + 1] + b1;
                if (MODE == 1) {
                    float2 ad = *(const float2*)(addend + off);
                    v.x += ad.x; v.y += ad.y;
                }
                *(float2*)(C + off) = v;
            }
        }
    }
}

// ---------------- score: score[b,h,t] = SCALE*(dot(X[b,t,:]*s[b,:], Wl[h,:]) + bl[h]) + madd
__global__ __launch_bounds__(256)
void score_kernel(const float* __restrict__ X, const float* __restrict__ Wl,
                  const float* __restrict__ bl, const float* __restrict__ s,
                  const float* __restrict__ mask, float* __restrict__ score)
{
    __shared__ float xs[H_];
    const int bt = blockIdx.x;
    const int b  = bt / T_;
    const int t  = bt % T_;
    const int tid = threadIdx.x;

    const float* xrow = X + (size_t)bt * H_;
    if (s) {
        const float* sb = s + (size_t)b * H_;
        for (int j = tid; j < H_; j += 256) xs[j] = xrow[j] * sb[j];
    } else {
        for (int j = tid; j < H_; j += 256) xs[j] = xrow[j];
    }
    __syncthreads();

    const float madd = (1.f - mask[bt]) * -10000.f;
    const int warp = tid >> 5, lane = tid & 31;
    #pragma unroll
    for (int h = warp; h < NH_; h += 8) {
        const float* w = Wl + (size_t)h * H_;
        float sum = 0.f;
        for (int j = lane; j < H_; j += 32) sum = fmaf(xs[j], w[j], sum);
        #pragma unroll
        for (int o = 16; o; o >>= 1) sum += __shfl_xor_sync(0xffffffffu, sum, o);
        if (lane == 0)
            score[((size_t)b * NH_ + h) * T_ + t] = SCALE * (sum + bl[h]) + madd;
    }
}

// ---------------- softmax stats per (b,h): max + 1/sum(exp)
__global__ __launch_bounds__(256)
void stats_kernel(const float* __restrict__ score, float2* __restrict__ stat)
{
    __shared__ float red[256];
    const int bh = blockIdx.x;
    const int tid = threadIdx.x;
    const float* sc = score + (size_t)bh * T_;

    float mx = -INFINITY;
    for (int t = tid; t < T_; t += 256) mx = fmaxf(mx, sc[t]);
    red[tid] = mx; __syncthreads();
    #pragma unroll
    for (int s2 = 128; s2; s2 >>= 1) {
        if (tid < s2) red[tid] = fmaxf(red[tid], red[tid + s2]);
        __syncthreads();
    }
    mx = red[0]; __syncthreads();

    float sum = 0.f;
    for (int t = tid; t < T_; t += 256) sum += __expf(sc[t] - mx);
    red[tid] = sum; __syncthreads();
    #pragma unroll
    for (int s2 = 128; s2; s2 >>= 1) {
        if (tid < s2) red[tid] += red[tid + s2];
        __syncthreads();
    }
    if (tid == 0) stat[bh] = make_float2(mx, 1.f / red[0]);
}

// ---------------- chunked pooling
__global__ __launch_bounds__(256)
void pool_kernel(const float* __restrict__ score, const float2* __restrict__ stat,
                 const float* __restrict__ X, float* __restrict__ part)
{
    __shared__ float red[256];
    const int chunk = blockIdx.x;
    const int bh = blockIdx.y;
    const int b = bh / NH_, h = bh % NH_;
    const int tid = threadIdx.x;
    const int d = tid & 63, tg = tid >> 6;

    const float mx = stat[bh].x;
    const float* sc = score + (size_t)bh * T_ + (size_t)chunk * TCH;
    const float* xp = X + (size_t)b * T_ * H_ + (size_t)chunk * TCH * H_ + h * HD_ + d;

    float acc = 0.f;
    for (int t = tg; t < TCH; t += 4)
        acc = fmaf(__expf(sc[t] - mx), xp[(size_t)t * H_], acc);
    red[tid] = acc; __syncthreads();
    if (tg == 0) {
        float v = red[d] + red[64 + d] + red[128 + d] + red[192 + d];
        part[((size_t)bh * NCH + chunk) * HD_ + d] = v;
    }
}

// ---------------- final pooled reduce
__global__ __launch_bounds__(64)
void reduce_pool(const float* __restrict__ part, const float2* __restrict__ stat,
                 const float* __restrict__ mul, float* __restrict__ pooled)
{
    const int bh = blockIdx.x;
    const int b = bh / NH_, h = bh % NH_;
    const int d = threadIdx.x;
    const float inv = stat[bh].y;
    float v = 0.f;
    #pragma unroll
    for (int c = 0; c < NCH; c++)
        v += part[((size_t)bh * NCH + c) * HD_ + d];
    v *= inv;
    const size_t o = (size_t)b * H_ + h * HD_ + d;
    if (mul) v *= mul[o];
    pooled[o] = v;
}

// ---------------- launch ----------------
extern "C" void kernel_launch(void* const* d_in, const int* in_sizes, int n_in,
                              void* d_out, int out_size)
{
    const float* hs   = (const float*)d_in[0];
    const float* mask = (const float*)d_in[1];
    const float* Wq   = (const float*)d_in[2];
    const float* bq   = (const float*)d_in[3];
    const float* Wk   = (const float*)d_in[4];
    const float* bk   = (const float*)d_in[5];
    const float* Wql  = (const float*)d_in[6];
    const float* bql  = (const float*)d_in[7];
    const float* Wkl  = (const float*)d_in[8];
    const float* bkl  = (const float*)d_in[9];
    const float* Wt   = (const float*)d_in[10];
    const float* bt   = (const float*)d_in[11];
    float* out = (float*)d_out;

    float *q, *k, *score, *pq, *pk, *part;
    float2* stat;
    cudaGetSymbolAddress((void**)&q, g_q);
    cudaGetSymbolAddress((void**)&k, g_k);
    cudaGetSymbolAddress((void**)&score, g_score);
    cudaGetSymbolAddress((void**)&pq, g_pq);
    cudaGetSymbolAddress((void**)&pk, g_pk);
    cudaGetSymbolAddress((void**)&stat, g_stat);
    cudaGetSymbolAddress((void**)&part, g_part);

    // 1+2. q = hs@Wq^T + bq ; k = hs@Wk^T + bk  (fused dual-output GEMM)
    gemm_tc<0><<<dim3(2 * H_ / BN, MTOT / BM), 256>>>(
        hs, Wq, bq, Wk, bk, nullptr, nullptr, q, k);

    // 3. pooled_q
    score_kernel<<<MTOT, 256>>>(q, Wql, bql, nullptr, mask, score);
    stats_kernel<<<B_ * NH_, 256>>>(score, stat);
    pool_kernel<<<dim3(NCH, B_ * NH_), 256>>>(score, stat, q, part);
    reduce_pool<<<B_ * NH_, 64>>>(part, stat, nullptr, pq);

    // 4. pooled_k (k rows modulated by pq; final multiply by pq)
    score_kernel<<<MTOT, 256>>>(k, Wkl, bkl, pq, mask, score);
    stats_kernel<<<B_ * NH_, 256>>>(score, stat);
    pool_kernel<<<dim3(NCH, B_ * NH_), 256>>>(score, stat, k, part);
    reduce_pool<<<B_ * NH_, 64>>>(part, stat, pq, pk);

    // 5. out = (q * pk_row) @ Wt^T + bt + q
    gemm_tc<1><<<dim3(H_ / BN, MTOT / BM), 256>>>(
        q, Wt, bt, nullptr, nullptr, pk, q, out, nullptr);
}

// round 5
// speedup vs baseline: 3.5405x; 1.3946x over previous
#include <cuda_runtime.h>
#include <cuda_fp16.h>
#include <cstdint>
#include <math.h>

// Problem constants
#define B_   8
#define T_   4096
#define H_   1024
#define NH_  16
#define HD_  64
#define MTOT (B_ * T_)          // 32768
#define SCALE 0.125f            // 1/sqrt(64)
#define NCH  8
#define TCH  (T_ / NCH)         // 512
#define WTS_SCALE 256.0f
#define WTS_INV   (1.0f / 256.0f)

// ---------------- scratch ----------------
__device__ __half g_hsh[(size_t)MTOT * H_];       // 64 MB
__device__ __half g_qh[(size_t)MTOT * H_];        // 64 MB
__device__ __half g_kh[(size_t)MTOT * H_];        // 64 MB
__device__ __half g_wqh[H_ * H_];
__device__ __half g_wkh[H_ * H_];
__device__ __half g_wts[(size_t)B_ * H_ * H_];    // 16 MB, per-batch scaled Wt
__device__ float  g_score[(size_t)B_ * NH_ * T_]; // 2 MB
__device__ float  g_pq[B_ * H_];
__device__ float  g_pk[B_ * H_];
__device__ float2 g_stat[B_ * NH_];
__device__ float  g_part[B_ * NH_ * NCH * HD_];

// ---------------- fp32 -> fp16 convert (8 elems/thread) ----------------
__global__ __launch_bounds__(256)
void cvt_kernel(const float* __restrict__ src, __half* __restrict__ dst, int n8)
{
    int i = blockIdx.x * 256 + threadIdx.x;
    if (i >= n8) return;
    float4 a = ((const float4*)src)[2 * i];
    float4 b = ((const float4*)src)[2 * i + 1];
    __half2 h0 = __floats2half2_rn(a.x, a.y), h1 = __floats2half2_rn(a.z, a.w);
    __half2 h2 = __floats2half2_rn(b.x, b.y), h3 = __floats2half2_rn(b.z, b.w);
    uint4 v;
    v.x = reinterpret_cast<uint32_t&>(h0);
    v.y = reinterpret_cast<uint32_t&>(h1);
    v.z = reinterpret_cast<uint32_t&>(h2);
    v.w = reinterpret_cast<uint32_t&>(h3);
    ((uint4*)dst)[i] = v;
}

// ---------------- wts[b,n,j] = fp16(Wt[n,j] * pk[b,j] * WTS_SCALE) ----------------
__global__ __launch_bounds__(256)
void scalew_kernel(const float* __restrict__ Wt, const float* __restrict__ pk,
                   __half* __restrict__ wts)
{
    size_t i = (size_t)blockIdx.x * 256 + threadIdx.x;   // handles 4 elems
    size_t e = i * 4;
    int b = (int)(e >> 20);                 // / (H_*H_)
    int r = (int)(e & (H_ * H_ - 1));       // n*H + j
    int j = r & (H_ - 1);
    float4 w = *(const float4*)(Wt + r);
    float4 s = *(const float4*)(pk + (size_t)b * H_ + j);
    __half2 lo = __floats2half2_rn(w.x * s.x * WTS_SCALE, w.y * s.y * WTS_SCALE);
    __half2 hi = __floats2half2_rn(w.z * s.z * WTS_SCALE, w.w * s.w * WTS_SCALE);
    uint2 v;
    v.x = reinterpret_cast<uint32_t&>(lo);
    v.y = reinterpret_cast<uint32_t&>(hi);
    *(uint2*)(wts + e) = v;
}

// =================================================================
// Pure fp16 GEMM: mma.sync m16n8k16 + ldmatrix + cp.async 2-stage
// A [M,K] half, W [N,K] half.
// MODE 0: dual output (W0->C0h, W1->C1h), bias, half out.
// MODE 1: W indexed per-batch (wts + b*H*H), out fp32 = acc*WTS_INV + bias + addend(half)
// =================================================================
#define BM 128
#define BN 128
#define BKK 32
#define ROWH 40                 // 32 + 8 pad halves -> 80B stride, ldmatrix conflict-free

__device__ __forceinline__ void cp16(void* smem, const void* gmem) {
    uint32_t s = (uint32_t)__cvta_generic_to_shared(smem);
    asm volatile("cp.async.cg.shared.global [%0], [%1], 16;" :: "r"(s), "l"(gmem));
}
__device__ __forceinline__ void cp_commit() { asm volatile("cp.async.commit_group;"); }
template <int N> __device__ __forceinline__ void cp_wait() {
    asm volatile("cp.async.wait_group %0;" :: "n"(N));
}

__device__ __forceinline__ void ldsm_x4(uint32_t* r, const void* p) {
    uint32_t addr = (uint32_t)__cvta_generic_to_shared(p);
    asm volatile("ldmatrix.sync.aligned.m8n8.x4.shared.b16 {%0,%1,%2,%3}, [%4];"
                 : "=r"(r[0]), "=r"(r[1]), "=r"(r[2]), "=r"(r[3]) : "r"(addr));
}

__device__ __forceinline__ void mma_f16(float* c, const uint32_t* a, const uint32_t* b) {
    asm volatile(
        "mma.sync.aligned.m16n8k16.row.col.f32.f16.f16.f32 "
        "{%0,%1,%2,%3}, {%4,%5,%6,%7}, {%8,%9}, {%0,%1,%2,%3};"
        : "+f"(c[0]), "+f"(c[1]), "+f"(c[2]), "+f"(c[3])
        : "r"(a[0]), "r"(a[1]), "r"(a[2]), "r"(a[3]),
          "r"(b[0]), "r"(b[1]));
}

template <int MODE>
__global__ __launch_bounds__(256, 2)
void gemm_h(const __half* __restrict__ A,
            const __half* __restrict__ W0, const float* __restrict__ bias0,
            const __half* __restrict__ W1, const float* __restrict__ bias1,
            const __half* __restrict__ addend,
            __half* __restrict__ C0h, __half* __restrict__ C1h,
            float* __restrict__ Cf)
{
    const int K = H_, N = H_;
    __shared__ __half As[2][BM][ROWH];
    __shared__ __half Bs[2][BN][ROWH];

    const int tid = threadIdx.x;
    const int bm  = blockIdx.y * BM;

    const __half* W = W0; const float* bias = bias0; __half* Ch = C0h;
    int bn;
    if (MODE == 0) {
        int bx = blockIdx.x;
        const int half_ = N / BN;
        if (bx >= half_) { W = W1; bias = bias1; Ch = C1h; bn = (bx - half_) * BN; }
        else bn = bx * BN;
    } else {
        bn = blockIdx.x * BN;
        W = W0 + (size_t)(bm / T_) * H_ * H_;   // per-batch scaled Wt
    }

    // cp.async chunk mapping: 512 chunks of 16B per tile; thread does 2 (A) + 2 (B)
    // chunk c: row = c>>2, col8 = (c&3)*8 halves
    const int wid = tid >> 5, lane = tid & 31;
    const int warp_m = wid >> 2, warp_n = wid & 3;
    const int gid = lane >> 2, lm = lane & 3;

    const int a_r = (lane & 7) + ((lane >> 3) & 1) * 8;
    const int a_c = (lane >> 4) * 8;
    const int b_r = (lane & 7) + ((lane >> 4) & 1) * 8;
    const int b_c = ((lane >> 3) & 1) * 8;

    float acc[4][4][4];
    #pragma unroll
    for (int i = 0; i < 4; i++)
        #pragma unroll
        for (int j = 0; j < 4; j++)
            #pragma unroll
            for (int r = 0; r < 4; r++) acc[i][j][r] = 0.f;

    auto issue_copy = [&](int kt, int s) {
        const int k0 = kt * BKK;
        #pragma unroll
        for (int l = 0; l < 2; l++) {
            int c = l * 256 + tid;
            int row = c >> 2, col8 = (c & 3) * 8;
            cp16(&As[s][row][col8], A + (size_t)(bm + row) * K + k0 + col8);
        }
        #pragma unroll
        for (int l = 0; l < 2; l++) {
            int c = l * 256 + tid;
            int row = c >> 2, col8 = (c & 3) * 8;
            cp16(&Bs[s][row][col8], W + (size_t)(bn + row) * K + k0 + col8);
        }
    };

    issue_copy(0, 0);
    cp_commit();

    const int KT = K / BKK;   // 32
    for (int kt = 0; kt < KT; kt++) {
        if (kt + 1 < KT) issue_copy(kt + 1, (kt + 1) & 1);
        cp_commit();
        cp_wait<1>();
        __syncthreads();

        const int s = kt & 1;
        #pragma unroll
        for (int kk = 0; kk < 2; kk++) {
            const int kb = kk * 16;
            uint32_t af[4][4], bf[4][2];
            #pragma unroll
            for (int mt = 0; mt < 4; mt++)
                ldsm_x4(af[mt], &As[s][warp_m * 64 + mt * 16 + a_r][kb + a_c]);
            #pragma unroll
            for (int ntp = 0; ntp < 2; ntp++) {
                uint32_t r4[4];
                ldsm_x4(r4, &Bs[s][warp_n * 32 + ntp * 16 + b_r][kb + b_c]);
                bf[ntp * 2 + 0][0] = r4[0]; bf[ntp * 2 + 0][1] = r4[1];
                bf[ntp * 2 + 1][0] = r4[2]; bf[ntp * 2 + 1][1] = r4[3];
            }
            #pragma unroll
            for (int mt = 0; mt < 4; mt++)
                #pragma unroll
                for (int nt = 0; nt < 4; nt++)
                    mma_f16(acc[mt][nt], af[mt], bf[nt]);
        }
        __syncthreads();
    }

    // epilogue
    #pragma unroll
    for (int mt = 0; mt < 4; mt++) {
        #pragma unroll
        for (int nt = 0; nt < 4; nt++) {
            int row0 = bm + warp_m * 64 + mt * 16 + gid;
            int col  = bn + warp_n * 32 + nt * 8 + lm * 2;
            float b0 = bias[col], b1 = bias[col + 1];
            #pragma unroll
            for (int hh = 0; hh < 2; hh++) {
                int row = row0 + hh * 8;
                size_t off = (size_t)row * N + col;
                if (MODE == 0) {
                    __half2 v = __floats2half2_rn(acc[mt][nt][hh * 2 + 0] + b0,
                                                  acc[mt][nt][hh * 2 + 1] + b1);
                    *(__half2*)(Ch + off) = v;
                } else {
                    __half2 ad = *(const __half2*)(addend + off);
                    float2 v;
                    v.x = acc[mt][nt][hh * 2 + 0] * WTS_INV + b0 + __low2float(ad);
                    v.y = acc[mt][nt][hh * 2 + 1] * WTS_INV + b1 + __high2float(ad);
                    *(float2*)(Cf + off) = v;
                }
            }
        }
    }
}

// ---------------- score: score[b,h,t] = SCALE*(dot(X[b,t,:]*s[b,:], Wl[h,:]) + bl[h]) + madd
__global__ __launch_bounds__(256)
void score_kernel(const __half* __restrict__ X, const float* __restrict__ Wl,
                  const float* __restrict__ bl, const float* __restrict__ s,
                  const float* __restrict__ mask, float* __restrict__ score)
{
    __shared__ float xs[H_];
    const int bt = blockIdx.x;
    const int b  = bt / T_;
    const int t  = bt % T_;
    const int tid = threadIdx.x;

    const __half2* xrow = (const __half2*)(X + (size_t)bt * H_);
    if (s) {
        const float* sb = s + (size_t)b * H_;
        for (int j2 = tid; j2 < H_ / 2; j2 += 256) {
            __half2 v = xrow[j2];
            xs[2 * j2]     = __low2float(v)  * sb[2 * j2];
            xs[2 * j2 + 1] = __high2float(v) * sb[2 * j2 + 1];
        }
    } else {
        for (int j2 = tid; j2 < H_ / 2; j2 += 256) {
            __half2 v = xrow[j2];
            xs[2 * j2]     = __low2float(v);
            xs[2 * j2 + 1] = __high2float(v);
        }
    }
    __syncthreads();

    const float madd = (1.f - mask[bt]) * -10000.f;
    const int warp = tid >> 5, lane = tid & 31;
    #pragma unroll
    for (int h = warp; h < NH_; h += 8) {
        const float* w = Wl + (size_t)h * H_;
        float sum = 0.f;
        for (int j = lane; j < H_; j += 32) sum = fmaf(xs[j], w[j], sum);
        #pragma unroll
        for (int o = 16; o; o >>= 1) sum += __shfl_xor_sync(0xffffffffu, sum, o);
        if (lane == 0)
            score[((size_t)b * NH_ + h) * T_ + t] = SCALE * (sum + bl[h]) + madd;
    }
}

// ---------------- softmax stats per (b,h): max + 1/sum(exp)
__global__ __launch_bounds__(256)
void stats_kernel(const float* __restrict__ score, float2* __restrict__ stat)
{
    __shared__ float red[256];
    const int bh = blockIdx.x;
    const int tid = threadIdx.x;
    const float* sc = score + (size_t)bh * T_;

    float mx = -INFINITY;
    for (int t = tid; t < T_; t += 256) mx = fmaxf(mx, sc[t]);
    red[tid] = mx; __syncthreads();
    #pragma unroll
    for (int s2 = 128; s2; s2 >>= 1) {
        if (tid < s2) red[tid] = fmaxf(red[tid], red[tid + s2]);
        __syncthreads();
    }
    mx = red[0]; __syncthreads();

    float sum = 0.f;
    for (int t = tid; t < T_; t += 256) sum += __expf(sc[t] - mx);
    red[tid] = sum; __syncthreads();
    #pragma unroll
    for (int s2 = 128; s2; s2 >>= 1) {
        if (tid < s2) red[tid] += red[tid + s2];
        __syncthreads();
    }
    if (tid == 0) stat[bh] = make_float2(mx, 1.f / red[0]);
}

// ---------------- chunked pooling
__global__ __launch_bounds__(256)
void pool_kernel(const float* __restrict__ score, const float2* __restrict__ stat,
                 const __half* __restrict__ X, float* __restrict__ part)
{
    __shared__ float red[256];
    const int chunk = blockIdx.x;
    const int bh = blockIdx.y;
    const int b = bh / NH_, h = bh % NH_;
    const int tid = threadIdx.x;
    const int d = tid & 63, tg = tid >> 6;

    const float mx = stat[bh].x;
    const float* sc = score + (size_t)bh * T_ + (size_t)chunk * TCH;
    const __half* xp = X + (size_t)b * T_ * H_ + (size_t)chunk * TCH * H_ + h * HD_ + d;

    float acc = 0.f;
    for (int t = tg; t < TCH; t += 4)
        acc = fmaf(__expf(sc[t] - mx), __half2float(xp[(size_t)t * H_]), acc);
    red[tid] = acc; __syncthreads();
    if (tg == 0) {
        float v = red[d] + red[64 + d] + red[128 + d] + red[192 + d];
        part[((size_t)bh * NCH + chunk) * HD_ + d] = v;
    }
}

// ---------------- final pooled reduce
__global__ __launch_bounds__(64)
void reduce_pool(const float* __restrict__ part, const float2* __restrict__ stat,
                 const float* __restrict__ mul, float* __restrict__ pooled)
{
    const int bh = blockIdx.x;
    const int b = bh / NH_, h = bh % NH_;
    const int d = threadIdx.x;
    const float inv = stat[bh].y;
    float v = 0.f;
    #pragma unroll
    for (int c = 0; c < NCH; c++)
        v += part[((size_t)bh * NCH + c) * HD_ + d];
    v *= inv;
    const size_t o = (size_t)b * H_ + h * HD_ + d;
    if (mul) v *= mul[o];
    pooled[o] = v;
}

// ---------------- launch ----------------
extern "C" void kernel_launch(void* const* d_in, const int* in_sizes, int n_in,
                              void* d_out, int out_size)
{
    const float* hs   = (const float*)d_in[0];
    const float* mask = (const float*)d_in[1];
    const float* Wq   = (const float*)d_in[2];
    const float* bq   = (const float*)d_in[3];
    const float* Wk   = (const float*)d_in[4];
    const float* bk   = (const float*)d_in[5];
    const float* Wql  = (const float*)d_in[6];
    const float* bql  = (const float*)d_in[7];
    const float* Wkl  = (const float*)d_in[8];
    const float* bkl  = (const float*)d_in[9];
    const float* Wt   = (const float*)d_in[10];
    const float* bt   = (const float*)d_in[11];
    float* out = (float*)d_out;

    __half *hsh, *qh, *kh, *wqh, *wkh, *wts;
    float *score, *pq, *pk, *part;
    float2* stat;
    cudaGetSymbolAddress((void**)&hsh, g_hsh);
    cudaGetSymbolAddress((void**)&qh, g_qh);
    cudaGetSymbolAddress((void**)&kh, g_kh);
    cudaGetSymbolAddress((void**)&wqh, g_wqh);
    cudaGetSymbolAddress((void**)&wkh, g_wkh);
    cudaGetSymbolAddress((void**)&wts, g_wts);
    cudaGetSymbolAddress((void**)&score, g_score);
    cudaGetSymbolAddress((void**)&pq, g_pq);
    cudaGetSymbolAddress((void**)&pk, g_pk);
    cudaGetSymbolAddress((void**)&stat, g_stat);
    cudaGetSymbolAddress((void**)&part, g_part);

    // 0. converts
    {
        int n8 = (int)((size_t)MTOT * H_ / 8);
        cvt_kernel<<<(n8 + 255) / 256, 256>>>(hs, hsh, n8);
        int w8 = H_ * H_ / 8;
        cvt_kernel<<<(w8 + 255) / 256, 256>>>(Wq, wqh, w8);
        cvt_kernel<<<(w8 + 255) / 256, 256>>>(Wk, wkh, w8);
    }

    // 1+2. q,k = hs @ {Wq,Wk}^T + bias (fused dual fp16 GEMM)
    gemm_h<0><<<dim3(2 * H_ / BN, MTOT / BM), 256>>>(
        hsh, wqh, bq, wkh, bk, nullptr, qh, kh, nullptr);

    // 3. pooled_q
    score_kernel<<<MTOT, 256>>>(qh, Wql, bql, nullptr, mask, score);
    stats_kernel<<<B_ * NH_, 256>>>(score, stat);
    pool_kernel<<<dim3(NCH, B_ * NH_), 256>>>(score, stat, qh, part);
    reduce_pool<<<B_ * NH_, 64>>>(part, stat, nullptr, pq);

    // 4. pooled_k
    score_kernel<<<MTOT, 256>>>(kh, Wkl, bkl, pq, mask, score);
    stats_kernel<<<B_ * NH_, 256>>>(score, stat);
    pool_kernel<<<dim3(NCH, B_ * NH_), 256>>>(score, stat, kh, part);
    reduce_pool<<<B_ * NH_, 64>>>(part, stat, pq, pk);

    // 4.5 wts[b] = fp16(Wt * pk[b] * 256)
    scalew_kernel<<<(B_ * H_ * H_ / 4 + 255) / 256, 256>>>(Wt, pk, wts);

    // 5. out = (q @ wts[b]^T) / 256 + bt + q
    gemm_h<1><<<dim3(H_ / BN, MTOT / BM), 256>>>(
        qh, wts, bt, nullptr, nullptr, qh, nullptr, nullptr, out);
}